// round 15
// baseline (speedup 1.0000x reference)
#include <cuda_runtime.h>
#include <cuda_bf16.h>
#include <math.h>
#include <stdint.h>

// Problem constants
#define LL 256
#define CC 128
#define HH 4
#define DD 32
#define NROWS (LL*LL)      // 65536
#define PLANE (LL*DD)      // 8192 floats per (s,h) plane

typedef unsigned long long u64;

__device__ __forceinline__ u64 f2pk(float lo, float hi) {
    u64 r; asm("mov.b64 %0, {%1, %2};" : "=l"(r) : "f"(lo), "f"(hi)); return r;
}
__device__ __forceinline__ void f2unpk(u64 v, float& lo, float& hi) {
    asm("mov.b64 {%0, %1}, %2;" : "=f"(lo), "=f"(hi) : "l"(v));
}
#define FMA2(d, a, b, c) \
    asm("fma.rn.f32x2 %0, %1, %2, %3;" : "=l"(d) : "l"(a), "l"(b), "l"(c))

__device__ __forceinline__ uint32_t smem_u32(const void* p) {
    uint32_t a;
    asm("{ .reg .u64 t; cvta.to.shared.u64 t, %1; cvt.u32.u64 %0, t; }"
        : "=r"(a) : "l"(p));
    return a;
}
__device__ __forceinline__ void ldsm_x4(uint32_t (&r)[4], uint32_t addr) {
    asm volatile("ldmatrix.sync.aligned.m8n8.x4.shared.b16 {%0,%1,%2,%3}, [%4];"
                 : "=r"(r[0]), "=r"(r[1]), "=r"(r[2]), "=r"(r[3]) : "r"(addr));
}
__device__ __forceinline__ void mma_bf16(float (&d)[4], const uint32_t (&a)[4],
                                         uint32_t b0, uint32_t b1) {
    asm volatile(
        "mma.sync.aligned.m16n8k16.row.col.f32.bf16.bf16.f32 "
        "{%0,%1,%2,%3}, {%4,%5,%6,%7}, {%8,%9}, {%0,%1,%2,%3};"
        : "+f"(d[0]), "+f"(d[1]), "+f"(d[2]), "+f"(d[3])
        : "r"(a[0]), "r"(a[1]), "r"(a[2]), "r"(a[3]), "r"(b0), "r"(b1));
}

// Swizzled byte offset into a [128 rows x 64 cols] bf16 tile (128B rows,
// 16B chunks, chunk ^= row&7 -> ldmatrix over 8 rows conflict-free).
__device__ __forceinline__ uint32_t swz64(int row, int col) {
    uint32_t chunk = (uint32_t)(((col >> 3) ^ row) & 7);
    return (uint32_t)row * 128 + (chunk << 4) + (uint32_t)(col & 7) * 2;
}

// Scratch (device globals — no allocation allowed)
__device__ float g_x[NROWS*CC];
__device__ float g_biasT[HH*LL*LL];    // pair bias transposed: [h][k][q]
__device__ float g_qraw[NROWS*CC];     // [s][h][l][d]
__device__ float g_kraw[NROWS*CC];
__device__ float g_vraw[NROWS*CC];
__device__ float g_qc[NROWS*CC];
__device__ float g_kc[NROWS*CC];
__device__ float g_vc[NROWS*CC];
__device__ float g_gate[NROWS*CC];
__device__ float g_wa[NROWS*CC];

// ---------------------------------------------------------------------------
// K1: LayerNorm + pair-bias (transposed store). One warp per (i,j) row.
// ---------------------------------------------------------------------------
__global__ __launch_bounds__(256) void ln_bias_kernel(
    const float* __restrict__ pa, const float* __restrict__ lng,
    const float* __restrict__ lnb, const float* __restrict__ wp)
{
    int warp = threadIdx.x >> 5, lane = threadIdx.x & 31;
    int r = blockIdx.x * 8 + warp;
    if (r >= NROWS) return;
    const float4* row = (const float4*)(pa + (size_t)r * CC);
    float4 v = row[lane];
    float s  = v.x + v.y + v.z + v.w;
    float sq = v.x*v.x + v.y*v.y + v.z*v.z + v.w*v.w;
    #pragma unroll
    for (int o = 16; o; o >>= 1) {
        s  += __shfl_xor_sync(0xffffffffu, s,  o);
        sq += __shfl_xor_sync(0xffffffffu, sq, o);
    }
    float mean = s * (1.f/128.f);
    float var  = sq * (1.f/128.f) - mean*mean;
    float rstd = rsqrtf(var + 1e-5f);
    float4 gg = ((const float4*)lng)[lane];
    float4 bb = ((const float4*)lnb)[lane];
    float4 xn;
    xn.x = (v.x - mean)*rstd*gg.x + bb.x;
    xn.y = (v.y - mean)*rstd*gg.y + bb.y;
    xn.z = (v.z - mean)*rstd*gg.z + bb.z;
    xn.w = (v.w - mean)*rstd*gg.w + bb.w;
    ((float4*)(g_x + (size_t)r * CC))[lane] = xn;

    int c0 = lane * 4;
    float4 w0 = ((const float4*)wp)[c0 + 0];
    float4 w1 = ((const float4*)wp)[c0 + 1];
    float4 w2 = ((const float4*)wp)[c0 + 2];
    float4 w3 = ((const float4*)wp)[c0 + 3];
    float p0 = xn.x*w0.x + xn.y*w1.x + xn.z*w2.x + xn.w*w3.x;
    float p1 = xn.x*w0.y + xn.y*w1.y + xn.z*w2.y + xn.w*w3.y;
    float p2 = xn.x*w0.z + xn.y*w1.z + xn.z*w2.z + xn.w*w3.z;
    float p3 = xn.x*w0.w + xn.y*w1.w + xn.z*w2.w + xn.w*w3.w;
    #pragma unroll
    for (int o = 16; o; o >>= 1) {
        p0 += __shfl_xor_sync(0xffffffffu, p0, o);
        p1 += __shfl_xor_sync(0xffffffffu, p1, o);
        p2 += __shfl_xor_sync(0xffffffffu, p2, o);
        p3 += __shfl_xor_sync(0xffffffffu, p3, o);
    }
    if (lane == 0) {
        int i = r >> 8, j = r & 255;
        g_biasT[0*65536 + j*256 + i] = p0;
        g_biasT[1*65536 + j*256 + i] = p1;
        g_biasT[2*65536 + j*256 + i] = p2;
        g_biasT[3*65536 + j*256 + i] = p3;
    }
}

// ---------------------------------------------------------------------------
// K2a: FUSED q/k/v/gate projection GEMM (HMMA bf16 split precision).
// A (layernormed x) staged ONCE per CTA (hi/lo, both K-halves, 64KB);
// loop over 4 weight matrices, staging W halves into a shared 32KB buffer.
// q/k/v scatter to [s][h][l][d]; gate -> sigmoid(+bg).
// smem total 96KB -> 2 CTAs/SM.
// ---------------------------------------------------------------------------
static constexpr int FO_A  = 0;          // AH0,AH1,AL0,AL1: 4 x 16KB
static constexpr int FO_WH = 65536;
static constexpr int FO_WL = 81920;
static constexpr int FUSED_SMEM = 98304;

__global__ __launch_bounds__(256, 2) void fused_qkvg_kernel(
    const float* __restrict__ A,
    const float* __restrict__ Wq, const float* __restrict__ Wk,
    const float* __restrict__ Wv, const float* __restrict__ Wg,
    const float* __restrict__ bg,
    float* __restrict__ outq, float* __restrict__ outk,
    float* __restrict__ outv, float* __restrict__ outg)
{
    extern __shared__ char smc[];
    uint32_t sb = smem_u32(smc);
    int t = threadIdx.x, wid = t >> 5, lane = t & 31;
    size_t rowbase = (size_t)blockIdx.x * 128;

    // ---- stage A once: both halves, hi/lo ----
    const float4* Ag = (const float4*)(A + rowbase * CC);
    #pragma unroll 4
    for (int i4 = t; i4 < 4096; i4 += 256) {
        int row = i4 >> 5, c4 = i4 & 31;
        int half = c4 >> 4, col = (c4 & 15) * 4;
        float4 a = Ag[i4];
        float av[4] = {a.x, a.y, a.z, a.w};
        int hb = half * 16384;
        #pragma unroll
        for (int p = 0; p < 2; p++) {
            float f0 = av[2*p], f1 = av[2*p+1];
            __nv_bfloat16 h0 = __float2bfloat16(f0);
            __nv_bfloat16 h1 = __float2bfloat16(f1);
            __nv_bfloat16 l0 = __float2bfloat16(f0 - __bfloat162float(h0));
            __nv_bfloat16 l1 = __float2bfloat16(f1 - __bfloat162float(h1));
            uint32_t off = swz64(row, col + 2*p);
            *(__nv_bfloat162*)(smc + FO_A + hb         + off) = __halves2bfloat162(h0, h1);
            *(__nv_bfloat162*)(smc + FO_A + hb + 32768 + off) = __halves2bfloat162(l0, l1);
        }
    }

    int warpRow = wid & 3, warpCol = wid >> 2;
    int lane15 = lane & 15, hs = lane >> 4;

    int aR0 = warpRow*32 + lane15, aR1 = aR0 + 16;
    uint32_t aRB0 = (uint32_t)aR0*128, aRx0 = (uint32_t)(aR0 & 7);
    uint32_t aRB1 = (uint32_t)aR1*128, aRx1 = (uint32_t)(aR1 & 7);
    uint32_t bRB[4], bRx[4];
    #pragma unroll
    for (int p = 0; p < 4; p++) {
        int nr = warpCol*64 + p*16 + lane15;
        bRB[p] = (uint32_t)nr*128; bRx[p] = (uint32_t)(nr & 7);
    }

    const float* Ws[4]  = {Wq, Wk, Wv, Wg};
    float* outs[4]      = {outq, outk, outv, outg};
    int groupID = lane >> 2, tig = lane & 3;

    #pragma unroll 1
    for (int w = 0; w < 4; w++) {
        const float* W = Ws[w];
        float acc[2][8][4];
        #pragma unroll
        for (int mt = 0; mt < 2; mt++)
            #pragma unroll
            for (int nt = 0; nt < 8; nt++)
                #pragma unroll
                for (int e = 0; e < 4; e++) acc[mt][nt][e] = 0.f;

        #pragma unroll 1
        for (int half = 0; half < 2; half++) {
            __syncthreads();   // A staged (first pass) / prev MMA done
            // stage W half transposed: Wt[c][k_local] (hi/lo, swizzled)
            #pragma unroll 4
            for (int i = t; i < 8192; i += 256) {
                int kl = i >> 7, c = i & 127;
                float wv = W[(size_t)(half*64 + kl) * CC + c];
                __nv_bfloat16 h = __float2bfloat16(wv);
                __nv_bfloat16 l = __float2bfloat16(wv - __bfloat162float(h));
                uint32_t off = swz64(c, kl);
                *(__nv_bfloat16*)(smc + FO_WH + off) = h;
                *(__nv_bfloat16*)(smc + FO_WL + off) = l;
            }
            __syncthreads();

            int hb = half * 16384;
            #pragma unroll 1
            for (int term = 0; term < 3; term++) {
                uint32_t uA = sb + FO_A + hb + ((term == 2) ? 32768 : 0);
                uint32_t uB = sb + ((term == 1) ? FO_WL : FO_WH);
                #pragma unroll
                for (int ks = 0; ks < 4; ks++) {
                    uint32_t ch = (uint32_t)((ks << 1) | hs);
                    uint32_t af[2][4], bf[4][4];
                    ldsm_x4(af[0], uA + aRB0 + (((ch ^ aRx0) & 7) << 4));
                    ldsm_x4(af[1], uA + aRB1 + (((ch ^ aRx1) & 7) << 4));
                    #pragma unroll
                    for (int p = 0; p < 4; p++)
                        ldsm_x4(bf[p], uB + bRB[p] + (((ch ^ bRx[p]) & 7) << 4));
                    #pragma unroll
                    for (int mt = 0; mt < 2; mt++)
                        #pragma unroll
                        for (int p = 0; p < 4; p++) {
                            mma_bf16(acc[mt][2*p],   af[mt], bf[p][0], bf[p][2]);
                            mma_bf16(acc[mt][2*p+1], af[mt], bf[p][1], bf[p][3]);
                        }
                }
            }
        }

        // ---- epilogue for weight w ----
        float* out = outs[w];
        #pragma unroll
        for (int mt = 0; mt < 2; mt++) {
            #pragma unroll
            for (int nt = 0; nt < 8; nt++) {
                int col = warpCol*64 + nt*8 + tig*2;
                #pragma unroll
                for (int hf = 0; hf < 2; hf++) {
                    size_t r = rowbase + warpRow*32 + mt*16 + groupID + hf*8;
                    float2 v = make_float2(acc[mt][nt][2*hf], acc[mt][nt][2*hf+1]);
                    if (w < 3) {
                        int si = (int)(r >> 8), l = (int)(r & 255);
                        int h = col >> 5, d = col & 31;
                        *(float2*)(out + ((size_t)(si*4 + h)*256 + l)*32 + d) = v;
                    } else {
                        float2 bb = *(const float2*)(bg + col);
                        v.x = 1.f/(1.f + __expf(-(v.x + bb.x)));
                        v.y = 1.f/(1.f + __expf(-(v.y + bb.y)));
                        *(float2*)(out + r*CC + col) = v;
                    }
                }
            }
        }
    }
}

// ---------------------------------------------------------------------------
// K2b: single GEMM (HMMA bf16 split precision), used for the final
// (gate*wa) @ wo + bo projection. K-split halves, 64KB smem, 2 CTAs/SM.
// ---------------------------------------------------------------------------
static constexpr int KO_AH = 0;
static constexpr int KO_AL = 16384;
static constexpr int KO_WH = 32768;
static constexpr int KO_WL = 49152;
static constexpr int MMA_SMEM = 65536;

__global__ __launch_bounds__(256, 2) void mma_gemm_kernel(
    const float* __restrict__ A, const float* __restrict__ mul,
    const float* __restrict__ W, const float* __restrict__ bvec,
    float* __restrict__ out)
{
    extern __shared__ char smc[];
    uint32_t sb = smem_u32(smc);
    int t = threadIdx.x, wid = t >> 5, lane = t & 31;
    size_t rowbase = (size_t)blockIdx.x * 128;

    int warpRow = wid & 3, warpCol = wid >> 2;
    int lane15 = lane & 15, hs = lane >> 4;

    int aR0 = warpRow*32 + lane15, aR1 = aR0 + 16;
    uint32_t aRB0 = (uint32_t)aR0*128, aRx0 = (uint32_t)(aR0 & 7);
    uint32_t aRB1 = (uint32_t)aR1*128, aRx1 = (uint32_t)(aR1 & 7);
    uint32_t bRB[4], bRx[4];
    #pragma unroll
    for (int p = 0; p < 4; p++) {
        int nr = warpCol*64 + p*16 + lane15;
        bRB[p] = (uint32_t)nr*128; bRx[p] = (uint32_t)(nr & 7);
    }

    float acc[2][8][4];
    #pragma unroll
    for (int mt = 0; mt < 2; mt++)
        #pragma unroll
        for (int nt = 0; nt < 8; nt++)
            #pragma unroll
            for (int e = 0; e < 4; e++) acc[mt][nt][e] = 0.f;

    const float4* Ag = (const float4*)(A + rowbase * CC);
    const float4* Mg = (const float4*)(mul + rowbase * CC);

    #pragma unroll 1
    for (int half = 0; half < 2; half++) {
        if (half) __syncthreads();

        #pragma unroll 2
        for (int i4 = t; i4 < 2048; i4 += 256) {
            int row = i4 >> 4, c4 = i4 & 15;
            float4 a = Ag[row*32 + half*16 + c4];
            float4 m = Mg[row*32 + half*16 + c4];
            a.x*=m.x; a.y*=m.y; a.z*=m.z; a.w*=m.w;
            int col = c4 * 4;
            float av[4] = {a.x, a.y, a.z, a.w};
            #pragma unroll
            for (int p = 0; p < 2; p++) {
                float f0 = av[2*p], f1 = av[2*p+1];
                __nv_bfloat16 h0 = __float2bfloat16(f0);
                __nv_bfloat16 h1 = __float2bfloat16(f1);
                __nv_bfloat16 l0 = __float2bfloat16(f0 - __bfloat162float(h0));
                __nv_bfloat16 l1 = __float2bfloat16(f1 - __bfloat162float(h1));
                uint32_t off = swz64(row, col + 2*p);
                *(__nv_bfloat162*)(smc + KO_AH + off) = __halves2bfloat162(h0, h1);
                *(__nv_bfloat162*)(smc + KO_AL + off) = __halves2bfloat162(l0, l1);
            }
        }
        #pragma unroll 4
        for (int i = t; i < 8192; i += 256) {
            int kl = i >> 7, c = i & 127;
            float wv = W[(size_t)(half*64 + kl) * CC + c];
            __nv_bfloat16 h = __float2bfloat16(wv);
            __nv_bfloat16 l = __float2bfloat16(wv - __bfloat162float(h));
            uint32_t off = swz64(c, kl);
            *(__nv_bfloat16*)(smc + KO_WH + off) = h;
            *(__nv_bfloat16*)(smc + KO_WL + off) = l;
        }
        __syncthreads();

        #pragma unroll 1
        for (int term = 0; term < 3; term++) {
            uint32_t uA = sb + ((term == 2) ? KO_AL : KO_AH);
            uint32_t uB = sb + ((term == 1) ? KO_WL : KO_WH);
            #pragma unroll
            for (int ks = 0; ks < 4; ks++) {
                uint32_t ch = (uint32_t)((ks << 1) | hs);
                uint32_t af[2][4], bf[4][4];
                ldsm_x4(af[0], uA + aRB0 + (((ch ^ aRx0) & 7) << 4));
                ldsm_x4(af[1], uA + aRB1 + (((ch ^ aRx1) & 7) << 4));
                #pragma unroll
                for (int p = 0; p < 4; p++)
                    ldsm_x4(bf[p], uB + bRB[p] + (((ch ^ bRx[p]) & 7) << 4));
                #pragma unroll
                for (int mt = 0; mt < 2; mt++)
                    #pragma unroll
                    for (int p = 0; p < 4; p++) {
                        mma_bf16(acc[mt][2*p],   af[mt], bf[p][0], bf[p][2]);
                        mma_bf16(acc[mt][2*p+1], af[mt], bf[p][1], bf[p][3]);
                    }
            }
        }
    }

    int groupID = lane >> 2, tig = lane & 3;
    #pragma unroll
    for (int mt = 0; mt < 2; mt++) {
        #pragma unroll
        for (int nt = 0; nt < 8; nt++) {
            int col = warpCol*64 + nt*8 + tig*2;
            float2 bb = *(const float2*)(bvec + col);
            #pragma unroll
            for (int hf = 0; hf < 2; hf++) {
                size_t r = rowbase + warpRow*32 + mt*16 + groupID + hf*8;
                float2 v = make_float2(acc[mt][nt][2*hf] + bb.x,
                                       acc[mt][nt][2*hf+1] + bb.y);
                *(float2*)(out + r*CC + col) = v;
            }
        }
    }
}

// ---------------------------------------------------------------------------
// K3: depthwise inception conv over the key axis per (s,h) plane.
// ---------------------------------------------------------------------------
__global__ __launch_bounds__(256) void conv_kernel(
    const float* __restrict__ in, float* __restrict__ out,
    const float* __restrict__ w3, const float* __restrict__ b3,
    const float* __restrict__ w5, const float* __restrict__ b5,
    const float* __restrict__ w7, const float* __restrict__ b7,
    float scale)
{
    __shared__ float sm[PLANE];
    int blk = blockIdx.x;
    const float4* ip = (const float4*)(in + (size_t)blk * PLANE);
    float4* sp = (float4*)sm;
    for (int i = threadIdx.x; i < PLANE/4; i += 256) sp[i] = ip[i];
    __syncthreads();

    int s = blk >> 2;
    int branch = s >> 6;
    int d = threadIdx.x & 31, lg = threadIdx.x >> 5;
    float* op = out + (size_t)blk * PLANE;

    if (branch == 0) {
        for (int l = lg*32; l < lg*32 + 32; l++)
            op[l*32 + d] = scale * sm[l*32 + d];
    } else {
        int ksz = 2*branch + 1;
        const float* w = (branch == 1 ? w3 : branch == 2 ? w5 : w7) + d * ksz;
        float bb = (branch == 1 ? b3 : branch == 2 ? b5 : b7)[d];
        float wr[7];
        for (int j = 0; j < ksz; j++) wr[j] = w[j];
        int pad = branch;
        for (int l = lg*32; l < lg*32 + 32; l++) {
            float acc = bb;
            for (int j = 0; j < ksz; j++) {
                int li = l + j - pad;
                if (li >= 0 && li < 256) acc += wr[j] * sm[li*32 + d];
            }
            op[l*32 + d] = acc * scale;
        }
    }
}

// ---------------------------------------------------------------------------
// K4: attention per (s,h) plane. TWO query rows per thread (128 threads).
// Single-pass softmax; f32x2-packed.
// ---------------------------------------------------------------------------
__global__ __launch_bounds__(128) void attn_kernel(
    const float* __restrict__ q, const float* __restrict__ k,
    const float* __restrict__ v, const float* __restrict__ mask,
    float* __restrict__ wa)
{
    extern __shared__ float sm[];
    float* Ksm = sm;
    float* Vsm = sm + 8192;
    float* msk = sm + 16384;
    int blk = blockIdx.x;
    int s = blk >> 2, h = blk & 3;
    size_t plane = (size_t)blk * PLANE;

    const float4* kp = (const float4*)(k + plane);
    const float4* vp = (const float4*)(v + plane);
    for (int i = threadIdx.x; i < PLANE/4; i += 128) {
        ((float4*)Ksm)[i] = kp[i];
        ((float4*)Vsm)[i] = vp[i];
    }
    for (int i = threadIdx.x; i < 256; i += 128) msk[i] = mask[i];
    __syncthreads();

    int q0 = threadIdx.x;
    u64 qa[16], qb[16];
    {
        const u64* p0 = (const u64*)(q + plane + (size_t)q0 * 32);
        const u64* p1 = (const u64*)(q + plane + (size_t)(q0 + 128) * 32);
        #pragma unroll
        for (int i = 0; i < 16; i++) { qa[i] = p0[i]; qb[i] = p1[i]; }
    }
    const float* b0 = g_biasT + (size_t)h * 65536 + q0;
    const float* b1 = b0 + 128;
    const float MASKVAL = -3.4028234663852886e34f;

    float ls0 = 0.f, ls1 = 0.f;
    u64 acc0[16], acc1[16];
    #pragma unroll
    for (int i = 0; i < 16; i++) { acc0[i] = 0ULL; acc1[i] = 0ULL; }

    #pragma unroll 2
    for (int kk = 0; kk < 256; kk++) {
        float bias0 = b0[kk*256];
        float bias1 = b1[kk*256];
        const ulonglong2* kr = (const ulonglong2*)(Ksm + kk*32);
        u64 d0a = 0ULL, d0b = 0ULL, d1a = 0ULL, d1b = 0ULL;
        #pragma unroll
        for (int j = 0; j < 8; j++) {
            ulonglong2 kq = kr[j];
            FMA2(d0a, qa[2*j],   kq.x, d0a);
            FMA2(d0b, qa[2*j+1], kq.y, d0b);
            FMA2(d1a, qb[2*j],   kq.x, d1a);
            FMA2(d1b, qb[2*j+1], kq.y, d1b);
        }
        float x0, x1, y0, y1;
        f2unpk(d0a, x0, x1); f2unpk(d0b, y0, y1);
        float dt0 = (x0 + x1) + (y0 + y1) + bias0;
        f2unpk(d1a, x0, x1); f2unpk(d1b, y0, y1);
        float dt1 = (x0 + x1) + (y0 + y1) + bias1;
        bool mk = (msk[kk] > 0.f);
        float e0 = __expf(mk ? dt0 : MASKVAL);
        float e1 = __expf(mk ? dt1 : MASKVAL);
        ls0 += e0; ls1 += e1;
        u64 e0p = f2pk(e0, e0);
        u64 e1p = f2pk(e1, e1);
        const ulonglong2* vr = (const ulonglong2*)(Vsm + kk*32);
        #pragma unroll
        for (int j = 0; j < 8; j++) {
            ulonglong2 vv = vr[j];
            FMA2(acc0[2*j],   e0p, vv.x, acc0[2*j]);
            FMA2(acc0[2*j+1], e0p, vv.y, acc0[2*j+1]);
            FMA2(acc1[2*j],   e1p, vv.x, acc1[2*j]);
            FMA2(acc1[2*j+1], e1p, vv.y, acc1[2*j+1]);
        }
    }

    float inv0 = 1.f / ls0, inv1 = 1.f / ls1;
    float* op0 = wa + ((size_t)(s*256 + q0)       * CC) + h * 32;
    float* op1 = wa + ((size_t)(s*256 + q0 + 128) * CC) + h * 32;
    #pragma unroll
    for (int j = 0; j < 8; j++) {
        float l0, h0, l1, h1;
        f2unpk(acc0[j*2],   l0, h0);
        f2unpk(acc0[j*2+1], l1, h1);
        *(float4*)(op0 + j*4) = make_float4(l0*inv0, h0*inv0, l1*inv0, h1*inv0);
        f2unpk(acc1[j*2],   l0, h0);
        f2unpk(acc1[j*2+1], l1, h1);
        *(float4*)(op1 + j*4) = make_float4(l0*inv1, h0*inv1, l1*inv1, h1*inv1);
    }
}

// ---------------------------------------------------------------------------
extern "C" void kernel_launch(void* const* d_in, const int* in_sizes, int n_in,
                              void* d_out, int out_size)
{
    const float* pair     = (const float*)d_in[0];
    const float* seq_mask = (const float*)d_in[1];
    const float* ln_g     = (const float*)d_in[2];
    const float* ln_b     = (const float*)d_in[3];
    const float* w_pair   = (const float*)d_in[4];
    const float* wq       = (const float*)d_in[5];
    const float* wk       = (const float*)d_in[6];
    const float* wv       = (const float*)d_in[7];
    const float* wg       = (const float*)d_in[8];
    const float* bg       = (const float*)d_in[9];
    const float* wo       = (const float*)d_in[10];
    const float* bo       = (const float*)d_in[11];
    const float* qw3 = (const float*)d_in[12]; const float* qb3 = (const float*)d_in[13];
    const float* qw5 = (const float*)d_in[14]; const float* qb5 = (const float*)d_in[15];
    const float* qw7 = (const float*)d_in[16]; const float* qb7 = (const float*)d_in[17];
    const float* kw3 = (const float*)d_in[18]; const float* kb3 = (const float*)d_in[19];
    const float* kw5 = (const float*)d_in[20]; const float* kb5 = (const float*)d_in[21];
    const float* kw7 = (const float*)d_in[22]; const float* kb7 = (const float*)d_in[23];
    const float* vw3 = (const float*)d_in[24]; const float* vb3 = (const float*)d_in[25];
    const float* vw5 = (const float*)d_in[26]; const float* vb5 = (const float*)d_in[27];
    const float* vw7 = (const float*)d_in[28]; const float* vb7 = (const float*)d_in[29];
    float* out = (float*)d_out;

    float *px, *pqr, *pkr, *pvr, *pqc, *pkc, *pvc, *pgate, *pwa;
    cudaGetSymbolAddress((void**)&px,   g_x);
    cudaGetSymbolAddress((void**)&pqr,  g_qraw);
    cudaGetSymbolAddress((void**)&pkr,  g_kraw);
    cudaGetSymbolAddress((void**)&pvr,  g_vraw);
    cudaGetSymbolAddress((void**)&pqc,  g_qc);
    cudaGetSymbolAddress((void**)&pkc,  g_kc);
    cudaGetSymbolAddress((void**)&pvc,  g_vc);
    cudaGetSymbolAddress((void**)&pgate, g_gate);
    cudaGetSymbolAddress((void**)&pwa,  g_wa);

    const size_t asm_ = (size_t)(2*PLANE + 256) * sizeof(float);
    cudaFuncSetAttribute(fused_qkvg_kernel, cudaFuncAttributeMaxDynamicSharedMemorySize, FUSED_SMEM);
    cudaFuncSetAttribute(mma_gemm_kernel, cudaFuncAttributeMaxDynamicSharedMemorySize, MMA_SMEM);
    cudaFuncSetAttribute(attn_kernel, cudaFuncAttributeMaxDynamicSharedMemorySize, (int)asm_);

    // 1. LN + pair bias
    ln_bias_kernel<<<NROWS/8, 256>>>(pair, ln_g, ln_b, w_pair);

    // 2. fused q/k/v/gate projections (A staged once)
    fused_qkvg_kernel<<<NROWS/128, 256, FUSED_SMEM>>>(
        px, wq, wk, wv, wg, bg, pqr, pkr, pvr, pgate);

    // 3. inception depthwise convs
    const float qscale = 0.17677669529663687f;  // 32^-0.5
    conv_kernel<<<LL*HH, 256>>>(pqr, pqc, qw3, qb3, qw5, qb5, qw7, qb7, qscale);
    conv_kernel<<<LL*HH, 256>>>(pkr, pkc, kw3, kb3, kw5, kb5, kw7, kb7, 1.f);
    conv_kernel<<<LL*HH, 256>>>(pvr, pvc, vw3, vb3, vw5, vb5, vw7, vb7, 1.f);

    // 4. attention
    attn_kernel<<<LL*HH, 128, asm_>>>(pqc, pkc, pvc, seq_mask, pwa);

    // 5. (gate * wa) @ wo + bo
    mma_gemm_kernel<<<NROWS/128, 256, MMA_SMEM>>>(pwa, pgate, wo, bo, out);
}

// round 16
// speedup vs baseline: 1.7611x; 1.7611x over previous
#include <cuda_runtime.h>
#include <cuda_bf16.h>
#include <math.h>
#include <stdint.h>

// Problem constants
#define LL 256
#define CC 128
#define HH 4
#define DD 32
#define NROWS (LL*LL)      // 65536
#define PLANE (LL*DD)      // 8192 floats per (s,h) plane

typedef unsigned long long u64;

__device__ __forceinline__ u64 f2pk(float lo, float hi) {
    u64 r; asm("mov.b64 %0, {%1, %2};" : "=l"(r) : "f"(lo), "f"(hi)); return r;
}
__device__ __forceinline__ void f2unpk(u64 v, float& lo, float& hi) {
    asm("mov.b64 {%0, %1}, %2;" : "=f"(lo), "=f"(hi) : "l"(v));
}
#define FMA2(d, a, b, c) \
    asm("fma.rn.f32x2 %0, %1, %2, %3;" : "=l"(d) : "l"(a), "l"(b), "l"(c))

__device__ __forceinline__ uint32_t smem_u32(const void* p) {
    uint32_t a;
    asm("{ .reg .u64 t; cvta.to.shared.u64 t, %1; cvt.u32.u64 %0, t; }"
        : "=r"(a) : "l"(p));
    return a;
}
__device__ __forceinline__ void ldsm_x4(uint32_t (&r)[4], uint32_t addr) {
    asm volatile("ldmatrix.sync.aligned.m8n8.x4.shared.b16 {%0,%1,%2,%3}, [%4];"
                 : "=r"(r[0]), "=r"(r[1]), "=r"(r[2]), "=r"(r[3]) : "r"(addr));
}
__device__ __forceinline__ void mma_bf16(float (&d)[4], const uint32_t (&a)[4],
                                         uint32_t b0, uint32_t b1) {
    asm volatile(
        "mma.sync.aligned.m16n8k16.row.col.f32.bf16.bf16.f32 "
        "{%0,%1,%2,%3}, {%4,%5,%6,%7}, {%8,%9}, {%0,%1,%2,%3};"
        : "+f"(d[0]), "+f"(d[1]), "+f"(d[2]), "+f"(d[3])
        : "r"(a[0]), "r"(a[1]), "r"(a[2]), "r"(a[3]), "r"(b0), "r"(b1));
}

// Swizzled byte offset into a [128 rows x 64 cols] bf16 tile (128B rows,
// 16B chunks, chunk ^= row&7 -> ldmatrix over 8 rows conflict-free).
__device__ __forceinline__ uint32_t swz64(int row, int col) {
    uint32_t chunk = (uint32_t)(((col >> 3) ^ row) & 7);
    return (uint32_t)row * 128 + (chunk << 4) + (uint32_t)(col & 7) * 2;
}

// Scratch (device globals — no allocation allowed)
__device__ float g_x[NROWS*CC];
__device__ float g_biasT[HH*LL*LL];    // pair bias transposed: [h][k][q]
__device__ float g_qraw[NROWS*CC];     // [s][h][l][d]
__device__ float g_kraw[NROWS*CC];
__device__ float g_vraw[NROWS*CC];
__device__ float g_qc[NROWS*CC];
__device__ float g_kc[NROWS*CC];
__device__ float g_vc[NROWS*CC];
__device__ float g_gate[NROWS*CC];
__device__ float g_wa[NROWS*CC];

// ---------------------------------------------------------------------------
// K1: LayerNorm + pair-bias (transposed store). One warp per (i,j) row.
// ---------------------------------------------------------------------------
__global__ __launch_bounds__(256) void ln_bias_kernel(
    const float* __restrict__ pa, const float* __restrict__ lng,
    const float* __restrict__ lnb, const float* __restrict__ wp)
{
    int warp = threadIdx.x >> 5, lane = threadIdx.x & 31;
    int r = blockIdx.x * 8 + warp;
    if (r >= NROWS) return;
    const float4* row = (const float4*)(pa + (size_t)r * CC);
    float4 v = row[lane];
    float s  = v.x + v.y + v.z + v.w;
    float sq = v.x*v.x + v.y*v.y + v.z*v.z + v.w*v.w;
    #pragma unroll
    for (int o = 16; o; o >>= 1) {
        s  += __shfl_xor_sync(0xffffffffu, s,  o);
        sq += __shfl_xor_sync(0xffffffffu, sq, o);
    }
    float mean = s * (1.f/128.f);
    float var  = sq * (1.f/128.f) - mean*mean;
    float rstd = rsqrtf(var + 1e-5f);
    float4 gg = ((const float4*)lng)[lane];
    float4 bb = ((const float4*)lnb)[lane];
    float4 xn;
    xn.x = (v.x - mean)*rstd*gg.x + bb.x;
    xn.y = (v.y - mean)*rstd*gg.y + bb.y;
    xn.z = (v.z - mean)*rstd*gg.z + bb.z;
    xn.w = (v.w - mean)*rstd*gg.w + bb.w;
    ((float4*)(g_x + (size_t)r * CC))[lane] = xn;

    int c0 = lane * 4;
    float4 w0 = ((const float4*)wp)[c0 + 0];
    float4 w1 = ((const float4*)wp)[c0 + 1];
    float4 w2 = ((const float4*)wp)[c0 + 2];
    float4 w3 = ((const float4*)wp)[c0 + 3];
    float p0 = xn.x*w0.x + xn.y*w1.x + xn.z*w2.x + xn.w*w3.x;
    float p1 = xn.x*w0.y + xn.y*w1.y + xn.z*w2.y + xn.w*w3.y;
    float p2 = xn.x*w0.z + xn.y*w1.z + xn.z*w2.z + xn.w*w3.z;
    float p3 = xn.x*w0.w + xn.y*w1.w + xn.z*w2.w + xn.w*w3.w;
    #pragma unroll
    for (int o = 16; o; o >>= 1) {
        p0 += __shfl_xor_sync(0xffffffffu, p0, o);
        p1 += __shfl_xor_sync(0xffffffffu, p1, o);
        p2 += __shfl_xor_sync(0xffffffffu, p2, o);
        p3 += __shfl_xor_sync(0xffffffffu, p3, o);
    }
    if (lane == 0) {
        int i = r >> 8, j = r & 255;
        g_biasT[0*65536 + j*256 + i] = p0;
        g_biasT[1*65536 + j*256 + i] = p1;
        g_biasT[2*65536 + j*256 + i] = p2;
        g_biasT[3*65536 + j*256 + i] = p3;
    }
}

// ---------------------------------------------------------------------------
// K2: GEMM via mma.sync (bf16 split precision, fp32 accum). R14-proven.
// K-split halves, 64KB smem, 2 CTAs/SM.
// mode 0: scatter to [s][h][l][d]; mode 1: sigmoid(+bvec); mode 2: +bvec.
// ---------------------------------------------------------------------------
static constexpr int KO_AH = 0;
static constexpr int KO_AL = 16384;
static constexpr int KO_WH = 32768;
static constexpr int KO_WL = 49152;
static constexpr int MMA_SMEM = 65536;

__global__ __launch_bounds__(256, 2) void mma_gemm_kernel(
    const float* __restrict__ A, const float* __restrict__ mul,
    const float* __restrict__ W, const float* __restrict__ bvec,
    float* __restrict__ out, int mode)
{
    extern __shared__ char smc[];
    uint32_t sb = smem_u32(smc);
    int t = threadIdx.x, wid = t >> 5, lane = t & 31;
    size_t rowbase = (size_t)blockIdx.x * 128;

    int warpRow = wid & 3, warpCol = wid >> 2;
    int lane15 = lane & 15, hs = lane >> 4;

    int aR0 = warpRow*32 + lane15, aR1 = aR0 + 16;
    uint32_t aRB0 = (uint32_t)aR0*128, aRx0 = (uint32_t)(aR0 & 7);
    uint32_t aRB1 = (uint32_t)aR1*128, aRx1 = (uint32_t)(aR1 & 7);
    uint32_t bRB[4], bRx[4];
    #pragma unroll
    for (int p = 0; p < 4; p++) {
        int nr = warpCol*64 + p*16 + lane15;
        bRB[p] = (uint32_t)nr*128; bRx[p] = (uint32_t)(nr & 7);
    }

    float acc[2][8][4];
    #pragma unroll
    for (int mt = 0; mt < 2; mt++)
        #pragma unroll
        for (int nt = 0; nt < 8; nt++)
            #pragma unroll
            for (int e = 0; e < 4; e++) acc[mt][nt][e] = 0.f;

    const float4* Ag = (const float4*)(A + rowbase * CC);
    const float4* Mg = mul ? (const float4*)(mul + rowbase * CC) : nullptr;

    #pragma unroll 1
    for (int half = 0; half < 2; half++) {
        if (half) __syncthreads();

        #pragma unroll 2
        for (int i4 = t; i4 < 2048; i4 += 256) {
            int row = i4 >> 4, c4 = i4 & 15;
            float4 a = Ag[row*32 + half*16 + c4];
            if (Mg) {
                float4 m = Mg[row*32 + half*16 + c4];
                a.x*=m.x; a.y*=m.y; a.z*=m.z; a.w*=m.w;
            }
            int col = c4 * 4;
            float av[4] = {a.x, a.y, a.z, a.w};
            #pragma unroll
            for (int p = 0; p < 2; p++) {
                float f0 = av[2*p], f1 = av[2*p+1];
                __nv_bfloat16 h0 = __float2bfloat16(f0);
                __nv_bfloat16 h1 = __float2bfloat16(f1);
                __nv_bfloat16 l0 = __float2bfloat16(f0 - __bfloat162float(h0));
                __nv_bfloat16 l1 = __float2bfloat16(f1 - __bfloat162float(h1));
                uint32_t off = swz64(row, col + 2*p);
                *(__nv_bfloat162*)(smc + KO_AH + off) = __halves2bfloat162(h0, h1);
                *(__nv_bfloat162*)(smc + KO_AL + off) = __halves2bfloat162(l0, l1);
            }
        }
        #pragma unroll 4
        for (int i = t; i < 8192; i += 256) {
            int kl = i >> 7, c = i & 127;
            float wv = W[(size_t)(half*64 + kl) * CC + c];
            __nv_bfloat16 h = __float2bfloat16(wv);
            __nv_bfloat16 l = __float2bfloat16(wv - __bfloat162float(h));
            uint32_t off = swz64(c, kl);
            *(__nv_bfloat16*)(smc + KO_WH + off) = h;
            *(__nv_bfloat16*)(smc + KO_WL + off) = l;
        }
        __syncthreads();

        #pragma unroll 1
        for (int term = 0; term < 3; term++) {
            uint32_t uA = sb + ((term == 2) ? KO_AL : KO_AH);
            uint32_t uB = sb + ((term == 1) ? KO_WL : KO_WH);
            #pragma unroll
            for (int ks = 0; ks < 4; ks++) {
                uint32_t ch = (uint32_t)((ks << 1) | hs);
                uint32_t af[2][4], bf[4][4];
                ldsm_x4(af[0], uA + aRB0 + (((ch ^ aRx0) & 7) << 4));
                ldsm_x4(af[1], uA + aRB1 + (((ch ^ aRx1) & 7) << 4));
                #pragma unroll
                for (int p = 0; p < 4; p++)
                    ldsm_x4(bf[p], uB + bRB[p] + (((ch ^ bRx[p]) & 7) << 4));
                #pragma unroll
                for (int mt = 0; mt < 2; mt++)
                    #pragma unroll
                    for (int p = 0; p < 4; p++) {
                        mma_bf16(acc[mt][2*p],   af[mt], bf[p][0], bf[p][2]);
                        mma_bf16(acc[mt][2*p+1], af[mt], bf[p][1], bf[p][3]);
                    }
            }
        }
    }

    int groupID = lane >> 2, tig = lane & 3;
    #pragma unroll
    for (int mt = 0; mt < 2; mt++) {
        #pragma unroll
        for (int nt = 0; nt < 8; nt++) {
            int col = warpCol*64 + nt*8 + tig*2;
            #pragma unroll
            for (int hf = 0; hf < 2; hf++) {
                size_t r = rowbase + warpRow*32 + mt*16 + groupID + hf*8;
                float2 v = make_float2(acc[mt][nt][2*hf], acc[mt][nt][2*hf+1]);
                if (mode == 0) {
                    int si = (int)(r >> 8), l = (int)(r & 255);
                    int h = col >> 5, d = col & 31;
                    *(float2*)(out + ((size_t)(si*4 + h)*256 + l)*32 + d) = v;
                } else if (mode == 1) {
                    float2 bb = *(const float2*)(bvec + col);
                    v.x = 1.f/(1.f + __expf(-(v.x + bb.x)));
                    v.y = 1.f/(1.f + __expf(-(v.y + bb.y)));
                    *(float2*)(out + r*CC + col) = v;
                } else {
                    float2 bb = *(const float2*)(bvec + col);
                    v.x += bb.x; v.y += bb.y;
                    *(float2*)(out + r*CC + col) = v;
                }
            }
        }
    }
}

// ---------------------------------------------------------------------------
// K3: fused q/k/v depthwise inception conv. grid = 3*1024; which = blk>>10.
// Register sliding window: 1 LDS + KSZ FMA per output (was KSZ LDS + KSZ FMA).
// ---------------------------------------------------------------------------
template<int KSZ>
__device__ __forceinline__ void conv_body(
    const float* sm, float* op, const float* w, const float* b,
    int d, int lg, float scale)
{
    const int PAD = KSZ/2;
    float wr[KSZ];
    #pragma unroll
    for (int j = 0; j < KSZ; j++) wr[j] = w[d*KSZ + j];
    float bb = b[d];
    int l0 = lg*32;
    float win[KSZ];
    #pragma unroll
    for (int j = 0; j < KSZ-1; j++) {
        int li = l0 - PAD + j;
        win[j] = (li >= 0 && li < 256) ? sm[li*32 + d] : 0.f;
    }
    #pragma unroll
    for (int l = 0; l < 32; l++) {
        int li = l0 + l + PAD;
        win[KSZ-1] = (li < 256) ? sm[li*32 + d] : 0.f;
        float acc = bb;
        #pragma unroll
        for (int j = 0; j < KSZ; j++) acc += wr[j] * win[j];
        op[(l0 + l)*32 + d] = acc * scale;
        #pragma unroll
        for (int j = 0; j < KSZ-1; j++) win[j] = win[j+1];
    }
}

__global__ __launch_bounds__(256) void conv3_kernel(
    const float* __restrict__ qin, const float* __restrict__ kin,
    const float* __restrict__ vin,
    float* __restrict__ qout, float* __restrict__ kout, float* __restrict__ vout,
    const float* __restrict__ qw3, const float* __restrict__ qb3,
    const float* __restrict__ qw5, const float* __restrict__ qb5,
    const float* __restrict__ qw7, const float* __restrict__ qb7,
    const float* __restrict__ kw3, const float* __restrict__ kb3,
    const float* __restrict__ kw5, const float* __restrict__ kb5,
    const float* __restrict__ kw7, const float* __restrict__ kb7,
    const float* __restrict__ vw3, const float* __restrict__ vb3,
    const float* __restrict__ vw5, const float* __restrict__ vb5,
    const float* __restrict__ vw7, const float* __restrict__ vb7)
{
    __shared__ float sm[PLANE];
    int which = blockIdx.x >> 10;           // 0=q, 1=k, 2=v
    int blk   = blockIdx.x & 1023;
    const float* in = (which == 0) ? qin : (which == 1) ? kin : vin;
    float* out      = (which == 0) ? qout : (which == 1) ? kout : vout;
    float scale     = (which == 0) ? 0.17677669529663687f : 1.f;

    int s = blk >> 2;
    int branch = s >> 6;                    // 0=id, 1=k3, 2=k5, 3=k7
    const float4* ip = (const float4*)(in + (size_t)blk * PLANE);
    float4* op4 = (float4*)(out + (size_t)blk * PLANE);

    if (branch == 0) {                      // identity: direct streamed copy
        #pragma unroll 4
        for (int i = threadIdx.x; i < PLANE/4; i += 256) {
            float4 v = ip[i];
            v.x *= scale; v.y *= scale; v.z *= scale; v.w *= scale;
            op4[i] = v;
        }
        return;
    }

    float4* sp = (float4*)sm;
    #pragma unroll 4
    for (int i = threadIdx.x; i < PLANE/4; i += 256) sp[i] = ip[i];
    __syncthreads();

    int d = threadIdx.x & 31, lg = threadIdx.x >> 5;
    float* op = out + (size_t)blk * PLANE;
    if (which == 0) {
        if (branch == 1)      conv_body<3>(sm, op, qw3, qb3, d, lg, scale);
        else if (branch == 2) conv_body<5>(sm, op, qw5, qb5, d, lg, scale);
        else                  conv_body<7>(sm, op, qw7, qb7, d, lg, scale);
    } else if (which == 1) {
        if (branch == 1)      conv_body<3>(sm, op, kw3, kb3, d, lg, scale);
        else if (branch == 2) conv_body<5>(sm, op, kw5, kb5, d, lg, scale);
        else                  conv_body<7>(sm, op, kw7, kb7, d, lg, scale);
    } else {
        if (branch == 1)      conv_body<3>(sm, op, vw3, vb3, d, lg, scale);
        else if (branch == 2) conv_body<5>(sm, op, vw5, vb5, d, lg, scale);
        else                  conv_body<7>(sm, op, vw7, vb7, d, lg, scale);
    }
}

// ---------------------------------------------------------------------------
// K4: attention per (s,h) plane. TWO query rows per thread (128 threads).
// Single-pass softmax; f32x2-packed. (R14-proven.)
// ---------------------------------------------------------------------------
__global__ __launch_bounds__(128) void attn_kernel(
    const float* __restrict__ q, const float* __restrict__ k,
    const float* __restrict__ v, const float* __restrict__ mask,
    float* __restrict__ wa)
{
    extern __shared__ float sm[];
    float* Ksm = sm;
    float* Vsm = sm + 8192;
    float* msk = sm + 16384;
    int blk = blockIdx.x;
    int s = blk >> 2, h = blk & 3;
    size_t plane = (size_t)blk * PLANE;

    const float4* kp = (const float4*)(k + plane);
    const float4* vp = (const float4*)(v + plane);
    for (int i = threadIdx.x; i < PLANE/4; i += 128) {
        ((float4*)Ksm)[i] = kp[i];
        ((float4*)Vsm)[i] = vp[i];
    }
    for (int i = threadIdx.x; i < 256; i += 128) msk[i] = mask[i];
    __syncthreads();

    int q0 = threadIdx.x;
    u64 qa[16], qb[16];
    {
        const u64* p0 = (const u64*)(q + plane + (size_t)q0 * 32);
        const u64* p1 = (const u64*)(q + plane + (size_t)(q0 + 128) * 32);
        #pragma unroll
        for (int i = 0; i < 16; i++) { qa[i] = p0[i]; qb[i] = p1[i]; }
    }
    const float* b0 = g_biasT + (size_t)h * 65536 + q0;
    const float* b1 = b0 + 128;
    const float MASKVAL = -3.4028234663852886e34f;

    float ls0 = 0.f, ls1 = 0.f;
    u64 acc0[16], acc1[16];
    #pragma unroll
    for (int i = 0; i < 16; i++) { acc0[i] = 0ULL; acc1[i] = 0ULL; }

    #pragma unroll 2
    for (int kk = 0; kk < 256; kk++) {
        float bias0 = b0[kk*256];
        float bias1 = b1[kk*256];
        const ulonglong2* kr = (const ulonglong2*)(Ksm + kk*32);
        u64 d0a = 0ULL, d0b = 0ULL, d1a = 0ULL, d1b = 0ULL;
        #pragma unroll
        for (int j = 0; j < 8; j++) {
            ulonglong2 kq = kr[j];
            FMA2(d0a, qa[2*j],   kq.x, d0a);
            FMA2(d0b, qa[2*j+1], kq.y, d0b);
            FMA2(d1a, qb[2*j],   kq.x, d1a);
            FMA2(d1b, qb[2*j+1], kq.y, d1b);
        }
        float x0, x1, y0, y1;
        f2unpk(d0a, x0, x1); f2unpk(d0b, y0, y1);
        float dt0 = (x0 + x1) + (y0 + y1) + bias0;
        f2unpk(d1a, x0, x1); f2unpk(d1b, y0, y1);
        float dt1 = (x0 + x1) + (y0 + y1) + bias1;
        bool mk = (msk[kk] > 0.f);
        float e0 = __expf(mk ? dt0 : MASKVAL);
        float e1 = __expf(mk ? dt1 : MASKVAL);
        ls0 += e0; ls1 += e1;
        u64 e0p = f2pk(e0, e0);
        u64 e1p = f2pk(e1, e1);
        const ulonglong2* vr = (const ulonglong2*)(Vsm + kk*32);
        #pragma unroll
        for (int j = 0; j < 8; j++) {
            ulonglong2 vv = vr[j];
            FMA2(acc0[2*j],   e0p, vv.x, acc0[2*j]);
            FMA2(acc0[2*j+1], e0p, vv.y, acc0[2*j+1]);
            FMA2(acc1[2*j],   e1p, vv.x, acc1[2*j]);
            FMA2(acc1[2*j+1], e1p, vv.y, acc1[2*j+1]);
        }
    }

    float inv0 = 1.f / ls0, inv1 = 1.f / ls1;
    float* op0 = wa + ((size_t)(s*256 + q0)       * CC) + h * 32;
    float* op1 = wa + ((size_t)(s*256 + q0 + 128) * CC) + h * 32;
    #pragma unroll
    for (int j = 0; j < 8; j++) {
        float l0, h0, l1, h1;
        f2unpk(acc0[j*2],   l0, h0);
        f2unpk(acc0[j*2+1], l1, h1);
        *(float4*)(op0 + j*4) = make_float4(l0*inv0, h0*inv0, l1*inv0, h1*inv0);
        f2unpk(acc1[j*2],   l0, h0);
        f2unpk(acc1[j*2+1], l1, h1);
        *(float4*)(op1 + j*4) = make_float4(l0*inv1, h0*inv1, l1*inv1, h1*inv1);
    }
}

// ---------------------------------------------------------------------------
extern "C" void kernel_launch(void* const* d_in, const int* in_sizes, int n_in,
                              void* d_out, int out_size)
{
    const float* pair     = (const float*)d_in[0];
    const float* seq_mask = (const float*)d_in[1];
    const float* ln_g     = (const float*)d_in[2];
    const float* ln_b     = (const float*)d_in[3];
    const float* w_pair   = (const float*)d_in[4];
    const float* wq       = (const float*)d_in[5];
    const float* wk       = (const float*)d_in[6];
    const float* wv       = (const float*)d_in[7];
    const float* wg       = (const float*)d_in[8];
    const float* bg       = (const float*)d_in[9];
    const float* wo       = (const float*)d_in[10];
    const float* bo       = (const float*)d_in[11];
    const float* qw3 = (const float*)d_in[12]; const float* qb3 = (const float*)d_in[13];
    const float* qw5 = (const float*)d_in[14]; const float* qb5 = (const float*)d_in[15];
    const float* qw7 = (const float*)d_in[16]; const float* qb7 = (const float*)d_in[17];
    const float* kw3 = (const float*)d_in[18]; const float* kb3 = (const float*)d_in[19];
    const float* kw5 = (const float*)d_in[20]; const float* kb5 = (const float*)d_in[21];
    const float* kw7 = (const float*)d_in[22]; const float* kb7 = (const float*)d_in[23];
    const float* vw3 = (const float*)d_in[24]; const float* vb3 = (const float*)d_in[25];
    const float* vw5 = (const float*)d_in[26]; const float* vb5 = (const float*)d_in[27];
    const float* vw7 = (const float*)d_in[28]; const float* vb7 = (const float*)d_in[29];
    float* out = (float*)d_out;

    float *px, *pqr, *pkr, *pvr, *pqc, *pkc, *pvc, *pgate, *pwa;
    cudaGetSymbolAddress((void**)&px,   g_x);
    cudaGetSymbolAddress((void**)&pqr,  g_qraw);
    cudaGetSymbolAddress((void**)&pkr,  g_kraw);
    cudaGetSymbolAddress((void**)&pvr,  g_vraw);
    cudaGetSymbolAddress((void**)&pqc,  g_qc);
    cudaGetSymbolAddress((void**)&pkc,  g_kc);
    cudaGetSymbolAddress((void**)&pvc,  g_vc);
    cudaGetSymbolAddress((void**)&pgate, g_gate);
    cudaGetSymbolAddress((void**)&pwa,  g_wa);

    const size_t asm_ = (size_t)(2*PLANE + 256) * sizeof(float);
    cudaFuncSetAttribute(mma_gemm_kernel, cudaFuncAttributeMaxDynamicSharedMemorySize, MMA_SMEM);
    cudaFuncSetAttribute(attn_kernel, cudaFuncAttributeMaxDynamicSharedMemorySize, (int)asm_);

    // 1. LN + pair bias
    ln_bias_kernel<<<NROWS/8, 256>>>(pair, ln_g, ln_b, w_pair);

    // 2. projections (separate launches — R14-proven; fusion regressed in R15)
    mma_gemm_kernel<<<NROWS/128, 256, MMA_SMEM>>>(px, nullptr, wq, nullptr, pqr, 0);
    mma_gemm_kernel<<<NROWS/128, 256, MMA_SMEM>>>(px, nullptr, wk, nullptr, pkr, 0);
    mma_gemm_kernel<<<NROWS/128, 256, MMA_SMEM>>>(px, nullptr, wv, nullptr, pvr, 0);
    mma_gemm_kernel<<<NROWS/128, 256, MMA_SMEM>>>(px, nullptr, wg, bg,      pgate, 1);

    // 3. fused q/k/v inception convs (register sliding window)
    conv3_kernel<<<3*LL*HH, 256>>>(pqr, pkr, pvr, pqc, pkc, pvc,
                                   qw3, qb3, qw5, qb5, qw7, qb7,
                                   kw3, kb3, kw5, kb5, kw7, kb7,
                                   vw3, vb3, vw5, vb5, vw7, vb7);

    // 4. attention
    attn_kernel<<<LL*HH, 128, asm_>>>(pqc, pkc, pvc, seq_mask, pwa);

    // 5. (gate * wa) @ wo + bo
    mma_gemm_kernel<<<NROWS/128, 256, MMA_SMEM>>>(pwa, pgate, wo, bo, out, 2);
}

// round 17
// speedup vs baseline: 1.8282x; 1.0381x over previous
#include <cuda_runtime.h>
#include <cuda_bf16.h>
#include <math.h>
#include <stdint.h>

// Problem constants
#define LL 256
#define CC 128
#define HH 4
#define DD 32
#define NROWS (LL*LL)      // 65536
#define PLANE (LL*DD)      // 8192 floats per (s,h) plane

typedef unsigned long long u64;

__device__ __forceinline__ u64 f2pk(float lo, float hi) {
    u64 r; asm("mov.b64 %0, {%1, %2};" : "=l"(r) : "f"(lo), "f"(hi)); return r;
}
__device__ __forceinline__ void f2unpk(u64 v, float& lo, float& hi) {
    asm("mov.b64 {%0, %1}, %2;" : "=f"(lo), "=f"(hi) : "l"(v));
}
#define FMA2(d, a, b, c) \
    asm("fma.rn.f32x2 %0, %1, %2, %3;" : "=l"(d) : "l"(a), "l"(b), "l"(c))

__device__ __forceinline__ uint32_t smem_u32(const void* p) {
    uint32_t a;
    asm("{ .reg .u64 t; cvta.to.shared.u64 t, %1; cvt.u32.u64 %0, t; }"
        : "=r"(a) : "l"(p));
    return a;
}
__device__ __forceinline__ void ldsm_x4(uint32_t (&r)[4], uint32_t addr) {
    asm volatile("ldmatrix.sync.aligned.m8n8.x4.shared.b16 {%0,%1,%2,%3}, [%4];"
                 : "=r"(r[0]), "=r"(r[1]), "=r"(r[2]), "=r"(r[3]) : "r"(addr));
}
__device__ __forceinline__ void mma_bf16(float (&d)[4], const uint32_t (&a)[4],
                                         uint32_t b0, uint32_t b1) {
    asm volatile(
        "mma.sync.aligned.m16n8k16.row.col.f32.bf16.bf16.f32 "
        "{%0,%1,%2,%3}, {%4,%5,%6,%7}, {%8,%9}, {%0,%1,%2,%3};"
        : "+f"(d[0]), "+f"(d[1]), "+f"(d[2]), "+f"(d[3])
        : "r"(a[0]), "r"(a[1]), "r"(a[2]), "r"(a[3]), "r"(b0), "r"(b1));
}

// Swizzled byte offset into a [128 rows x 64 cols] bf16 tile (128B rows,
// 16B chunks, chunk ^= row&7 -> ldmatrix over 8 rows conflict-free).
__device__ __forceinline__ uint32_t swz64(int row, int col) {
    uint32_t chunk = (uint32_t)(((col >> 3) ^ row) & 7);
    return (uint32_t)row * 128 + (chunk << 4) + (uint32_t)(col & 7) * 2;
}

// Scratch (device globals — no allocation allowed)
// Pre-converted A (layernormed x) in gemm tile layout:
//   byte offset = (block*2 + half)*16384 + swz64(row_in_block, k_local)
__device__ char g_xh[16777216];
__device__ char g_xl[16777216];
// Pre-converted weights, transposed+swizzled: widx*32768 + half*16384 + swz64(c, kl)
__device__ char g_wth[5*32768];
__device__ char g_wtl[5*32768];

__device__ float g_biasT[HH*LL*LL];    // pair bias transposed: [h][k][q]
__device__ float g_qraw[NROWS*CC];     // [s][h][l][d]
__device__ float g_kraw[NROWS*CC];
__device__ float g_vraw[NROWS*CC];
__device__ float g_qc[NROWS*CC];
__device__ float g_kc[NROWS*CC];
__device__ float g_vc[NROWS*CC];
__device__ float g_gate[NROWS*CC];
__device__ float g_wa[NROWS*CC];

// ---------------------------------------------------------------------------
// K0: weight prep — convert 5 weights to transposed swizzled hi/lo bf16.
// One CTA per weight.
// ---------------------------------------------------------------------------
__global__ __launch_bounds__(256) void wprep_kernel(
    const float* __restrict__ wq, const float* __restrict__ wk,
    const float* __restrict__ wv, const float* __restrict__ wg,
    const float* __restrict__ wo)
{
    int widx = blockIdx.x;
    const float* W = (widx == 0) ? wq : (widx == 1) ? wk :
                     (widx == 2) ? wv : (widx == 3) ? wg : wo;
    char* dh = g_wth + widx * 32768;
    char* dl = g_wtl + widx * 32768;
    for (int i = threadIdx.x; i < 16384; i += 256) {
        int k = i >> 7, c = i & 127;
        float wv_ = W[i];
        __nv_bfloat16 h = __float2bfloat16(wv_);
        __nv_bfloat16 l = __float2bfloat16(wv_ - __bfloat162float(h));
        int half = k >> 6, kl = k & 63;
        uint32_t off = (uint32_t)half * 16384 + swz64(c, kl);
        *(__nv_bfloat16*)(dh + off) = h;
        *(__nv_bfloat16*)(dl + off) = l;
    }
}

// ---------------------------------------------------------------------------
// K1: LayerNorm + pair-bias (transposed store) + hi/lo bf16 tile store.
// One warp per (i,j) row.
// ---------------------------------------------------------------------------
__global__ __launch_bounds__(256) void ln_bias_kernel(
    const float* __restrict__ pa, const float* __restrict__ lng,
    const float* __restrict__ lnb, const float* __restrict__ wp)
{
    int warp = threadIdx.x >> 5, lane = threadIdx.x & 31;
    int r = blockIdx.x * 8 + warp;
    if (r >= NROWS) return;
    const float4* row = (const float4*)(pa + (size_t)r * CC);
    float4 v = row[lane];
    float s  = v.x + v.y + v.z + v.w;
    float sq = v.x*v.x + v.y*v.y + v.z*v.z + v.w*v.w;
    #pragma unroll
    for (int o = 16; o; o >>= 1) {
        s  += __shfl_xor_sync(0xffffffffu, s,  o);
        sq += __shfl_xor_sync(0xffffffffu, sq, o);
    }
    float mean = s * (1.f/128.f);
    float var  = sq * (1.f/128.f) - mean*mean;
    float rstd = rsqrtf(var + 1e-5f);
    float4 gg = ((const float4*)lng)[lane];
    float4 bb = ((const float4*)lnb)[lane];
    float4 xn;
    xn.x = (v.x - mean)*rstd*gg.x + bb.x;
    xn.y = (v.y - mean)*rstd*gg.y + bb.y;
    xn.z = (v.z - mean)*rstd*gg.z + bb.z;
    xn.w = (v.w - mean)*rstd*gg.w + bb.w;

    // store xn as hi/lo bf16 in gemm tile layout
    {
        int c0 = lane * 4;
        int block = r >> 7, rowin = r & 127;
        int half = c0 >> 6, col0 = c0 & 63;
        uint32_t base = (uint32_t)(block*2 + half) * 16384;
        float xv[4] = {xn.x, xn.y, xn.z, xn.w};
        #pragma unroll
        for (int p = 0; p < 2; p++) {
            float f0 = xv[2*p], f1 = xv[2*p+1];
            __nv_bfloat16 h0 = __float2bfloat16(f0);
            __nv_bfloat16 h1 = __float2bfloat16(f1);
            __nv_bfloat16 l0 = __float2bfloat16(f0 - __bfloat162float(h0));
            __nv_bfloat16 l1 = __float2bfloat16(f1 - __bfloat162float(h1));
            uint32_t off = base + swz64(rowin, col0 + 2*p);
            *(__nv_bfloat162*)(g_xh + off) = __halves2bfloat162(h0, h1);
            *(__nv_bfloat162*)(g_xl + off) = __halves2bfloat162(l0, l1);
        }
    }

    int c0 = lane * 4;
    float4 w0 = ((const float4*)wp)[c0 + 0];
    float4 w1 = ((const float4*)wp)[c0 + 1];
    float4 w2 = ((const float4*)wp)[c0 + 2];
    float4 w3 = ((const float4*)wp)[c0 + 3];
    float p0 = xn.x*w0.x + xn.y*w1.x + xn.z*w2.x + xn.w*w3.x;
    float p1 = xn.x*w0.y + xn.y*w1.y + xn.z*w2.y + xn.w*w3.y;
    float p2 = xn.x*w0.z + xn.y*w1.z + xn.z*w2.z + xn.w*w3.z;
    float p3 = xn.x*w0.w + xn.y*w1.w + xn.z*w2.w + xn.w*w3.w;
    #pragma unroll
    for (int o = 16; o; o >>= 1) {
        p0 += __shfl_xor_sync(0xffffffffu, p0, o);
        p1 += __shfl_xor_sync(0xffffffffu, p1, o);
        p2 += __shfl_xor_sync(0xffffffffu, p2, o);
        p3 += __shfl_xor_sync(0xffffffffu, p3, o);
    }
    if (lane == 0) {
        int i = r >> 8, j = r & 255;
        g_biasT[0*65536 + j*256 + i] = p0;
        g_biasT[1*65536 + j*256 + i] = p1;
        g_biasT[2*65536 + j*256 + i] = p2;
        g_biasT[3*65536 + j*256 + i] = p3;
    }
}

// ---------------------------------------------------------------------------
// K2: GEMM via mma.sync (bf16 split precision, fp32 accum).
// A path: fast (pre-converted hi/lo copy) when afast!=0, else fp32*mul convert.
// W path: always pre-converted (widx into g_wth/g_wtl).
// K-split halves, 64KB smem, 2 CTAs/SM.
// mode 0: scatter to [s][h][l][d]; mode 1: sigmoid(+bvec); mode 2: +bvec.
// ---------------------------------------------------------------------------
static constexpr int KO_AH = 0;
static constexpr int KO_AL = 16384;
static constexpr int KO_WH = 32768;
static constexpr int KO_WL = 49152;
static constexpr int MMA_SMEM = 65536;

__global__ __launch_bounds__(256, 2) void mma_gemm_kernel(
    int afast, const float* __restrict__ A, const float* __restrict__ mul,
    int widx, const float* __restrict__ bvec,
    float* __restrict__ out, int mode)
{
    extern __shared__ char smc[];
    uint32_t sb = smem_u32(smc);
    int t = threadIdx.x, wid = t >> 5, lane = t & 31;
    int block = blockIdx.x;
    size_t rowbase = (size_t)block * 128;

    int warpRow = wid & 3, warpCol = wid >> 2;
    int lane15 = lane & 15, hs = lane >> 4;

    int aR0 = warpRow*32 + lane15, aR1 = aR0 + 16;
    uint32_t aRB0 = (uint32_t)aR0*128, aRx0 = (uint32_t)(aR0 & 7);
    uint32_t aRB1 = (uint32_t)aR1*128, aRx1 = (uint32_t)(aR1 & 7);
    uint32_t bRB[4], bRx[4];
    #pragma unroll
    for (int p = 0; p < 4; p++) {
        int nr = warpCol*64 + p*16 + lane15;
        bRB[p] = (uint32_t)nr*128; bRx[p] = (uint32_t)(nr & 7);
    }

    float acc[2][8][4];
    #pragma unroll
    for (int mt = 0; mt < 2; mt++)
        #pragma unroll
        for (int nt = 0; nt < 8; nt++)
            #pragma unroll
            for (int e = 0; e < 4; e++) acc[mt][nt][e] = 0.f;

    const float4* Ag = (const float4*)(A + rowbase * CC);
    const float4* Mg = mul ? (const float4*)(mul + rowbase * CC) : nullptr;

    #pragma unroll 1
    for (int half = 0; half < 2; half++) {
        if (half) __syncthreads();

        // ---- stage W (always pre-converted; pure uint4 copy) ----
        {
            const uint4* sWh = (const uint4*)(g_wth + widx*32768 + half*16384);
            const uint4* sWl = (const uint4*)(g_wtl + widx*32768 + half*16384);
            uint4* dWh = (uint4*)(smc + KO_WH);
            uint4* dWl = (uint4*)(smc + KO_WL);
            #pragma unroll 4
            for (int i = t; i < 1024; i += 256) { dWh[i] = sWh[i]; dWl[i] = sWl[i]; }
        }
        // ---- stage A ----
        if (afast) {
            const uint4* sAh = (const uint4*)(g_xh + (size_t)(block*2 + half)*16384);
            const uint4* sAl = (const uint4*)(g_xl + (size_t)(block*2 + half)*16384);
            uint4* dAh = (uint4*)(smc + KO_AH);
            uint4* dAl = (uint4*)(smc + KO_AL);
            #pragma unroll 4
            for (int i = t; i < 1024; i += 256) { dAh[i] = sAh[i]; dAl[i] = sAl[i]; }
        } else {
            #pragma unroll 2
            for (int i4 = t; i4 < 2048; i4 += 256) {
                int row = i4 >> 4, c4 = i4 & 15;
                float4 a = Ag[row*32 + half*16 + c4];
                if (Mg) {
                    float4 m = Mg[row*32 + half*16 + c4];
                    a.x*=m.x; a.y*=m.y; a.z*=m.z; a.w*=m.w;
                }
                int col = c4 * 4;
                float av[4] = {a.x, a.y, a.z, a.w};
                #pragma unroll
                for (int p = 0; p < 2; p++) {
                    float f0 = av[2*p], f1 = av[2*p+1];
                    __nv_bfloat16 h0 = __float2bfloat16(f0);
                    __nv_bfloat16 h1 = __float2bfloat16(f1);
                    __nv_bfloat16 l0 = __float2bfloat16(f0 - __bfloat162float(h0));
                    __nv_bfloat16 l1 = __float2bfloat16(f1 - __bfloat162float(h1));
                    uint32_t off = swz64(row, col + 2*p);
                    *(__nv_bfloat162*)(smc + KO_AH + off) = __halves2bfloat162(h0, h1);
                    *(__nv_bfloat162*)(smc + KO_AL + off) = __halves2bfloat162(l0, l1);
                }
            }
        }
        __syncthreads();

        #pragma unroll 1
        for (int term = 0; term < 3; term++) {
            uint32_t uA = sb + ((term == 2) ? KO_AL : KO_AH);
            uint32_t uB = sb + ((term == 1) ? KO_WL : KO_WH);
            #pragma unroll
            for (int ks = 0; ks < 4; ks++) {
                uint32_t ch = (uint32_t)((ks << 1) | hs);
                uint32_t af[2][4], bf[4][4];
                ldsm_x4(af[0], uA + aRB0 + (((ch ^ aRx0) & 7) << 4));
                ldsm_x4(af[1], uA + aRB1 + (((ch ^ aRx1) & 7) << 4));
                #pragma unroll
                for (int p = 0; p < 4; p++)
                    ldsm_x4(bf[p], uB + bRB[p] + (((ch ^ bRx[p]) & 7) << 4));
                #pragma unroll
                for (int mt = 0; mt < 2; mt++)
                    #pragma unroll
                    for (int p = 0; p < 4; p++) {
                        mma_bf16(acc[mt][2*p],   af[mt], bf[p][0], bf[p][2]);
                        mma_bf16(acc[mt][2*p+1], af[mt], bf[p][1], bf[p][3]);
                    }
            }
        }
    }

    int groupID = lane >> 2, tig = lane & 3;
    #pragma unroll
    for (int mt = 0; mt < 2; mt++) {
        #pragma unroll
        for (int nt = 0; nt < 8; nt++) {
            int col = warpCol*64 + nt*8 + tig*2;
            #pragma unroll
            for (int hf = 0; hf < 2; hf++) {
                size_t r = rowbase + warpRow*32 + mt*16 + groupID + hf*8;
                float2 v = make_float2(acc[mt][nt][2*hf], acc[mt][nt][2*hf+1]);
                if (mode == 0) {
                    int si = (int)(r >> 8), l = (int)(r & 255);
                    int h = col >> 5, d = col & 31;
                    *(float2*)(out + ((size_t)(si*4 + h)*256 + l)*32 + d) = v;
                } else if (mode == 1) {
                    float2 bb = *(const float2*)(bvec + col);
                    v.x = 1.f/(1.f + __expf(-(v.x + bb.x)));
                    v.y = 1.f/(1.f + __expf(-(v.y + bb.y)));
                    *(float2*)(out + r*CC + col) = v;
                } else {
                    float2 bb = *(const float2*)(bvec + col);
                    v.x += bb.x; v.y += bb.y;
                    *(float2*)(out + r*CC + col) = v;
                }
            }
        }
    }
}

// ---------------------------------------------------------------------------
// K3: fused q/k/v depthwise inception conv. grid = 3*1024; which = blk>>10.
// Register sliding window: 1 LDS + KSZ FMA per output.
// ---------------------------------------------------------------------------
template<int KSZ>
__device__ __forceinline__ void conv_body(
    const float* sm, float* op, const float* w, const float* b,
    int d, int lg, float scale)
{
    const int PAD = KSZ/2;
    float wr[KSZ];
    #pragma unroll
    for (int j = 0; j < KSZ; j++) wr[j] = w[d*KSZ + j];
    float bb = b[d];
    int l0 = lg*32;
    float win[KSZ];
    #pragma unroll
    for (int j = 0; j < KSZ-1; j++) {
        int li = l0 - PAD + j;
        win[j] = (li >= 0 && li < 256) ? sm[li*32 + d] : 0.f;
    }
    #pragma unroll
    for (int l = 0; l < 32; l++) {
        int li = l0 + l + PAD;
        win[KSZ-1] = (li < 256) ? sm[li*32 + d] : 0.f;
        float acc = bb;
        #pragma unroll
        for (int j = 0; j < KSZ; j++) acc += wr[j] * win[j];
        op[(l0 + l)*32 + d] = acc * scale;
        #pragma unroll
        for (int j = 0; j < KSZ-1; j++) win[j] = win[j+1];
    }
}

__global__ __launch_bounds__(256) void conv3_kernel(
    const float* __restrict__ qin, const float* __restrict__ kin,
    const float* __restrict__ vin,
    float* __restrict__ qout, float* __restrict__ kout, float* __restrict__ vout,
    const float* __restrict__ qw3, const float* __restrict__ qb3,
    const float* __restrict__ qw5, const float* __restrict__ qb5,
    const float* __restrict__ qw7, const float* __restrict__ qb7,
    const float* __restrict__ kw3, const float* __restrict__ kb3,
    const float* __restrict__ kw5, const float* __restrict__ kb5,
    const float* __restrict__ kw7, const float* __restrict__ kb7,
    const float* __restrict__ vw3, const float* __restrict__ vb3,
    const float* __restrict__ vw5, const float* __restrict__ vb5,
    const float* __restrict__ vw7, const float* __restrict__ vb7)
{
    __shared__ float sm[PLANE];
    int which = blockIdx.x >> 10;           // 0=q, 1=k, 2=v
    int blk   = blockIdx.x & 1023;
    const float* in = (which == 0) ? qin : (which == 1) ? kin : vin;
    float* out      = (which == 0) ? qout : (which == 1) ? kout : vout;
    float scale     = (which == 0) ? 0.17677669529663687f : 1.f;

    int s = blk >> 2;
    int branch = s >> 6;                    // 0=id, 1=k3, 2=k5, 3=k7
    const float4* ip = (const float4*)(in + (size_t)blk * PLANE);
    float4* op4 = (float4*)(out + (size_t)blk * PLANE);

    if (branch == 0) {
        #pragma unroll 4
        for (int i = threadIdx.x; i < PLANE/4; i += 256) {
            float4 v = ip[i];
            v.x *= scale; v.y *= scale; v.z *= scale; v.w *= scale;
            op4[i] = v;
        }
        return;
    }

    float4* sp = (float4*)sm;
    #pragma unroll 4
    for (int i = threadIdx.x; i < PLANE/4; i += 256) sp[i] = ip[i];
    __syncthreads();

    int d = threadIdx.x & 31, lg = threadIdx.x >> 5;
    float* op = out + (size_t)blk * PLANE;
    if (which == 0) {
        if (branch == 1)      conv_body<3>(sm, op, qw3, qb3, d, lg, scale);
        else if (branch == 2) conv_body<5>(sm, op, qw5, qb5, d, lg, scale);
        else                  conv_body<7>(sm, op, qw7, qb7, d, lg, scale);
    } else if (which == 1) {
        if (branch == 1)      conv_body<3>(sm, op, kw3, kb3, d, lg, scale);
        else if (branch == 2) conv_body<5>(sm, op, kw5, kb5, d, lg, scale);
        else                  conv_body<7>(sm, op, kw7, kb7, d, lg, scale);
    } else {
        if (branch == 1)      conv_body<3>(sm, op, vw3, vb3, d, lg, scale);
        else if (branch == 2) conv_body<5>(sm, op, vw5, vb5, d, lg, scale);
        else                  conv_body<7>(sm, op, vw7, vb7, d, lg, scale);
    }
}

// ---------------------------------------------------------------------------
// K4: attention per (s,h) plane. TWO query rows per thread (128 threads).
// Single-pass softmax; f32x2-packed. (R14-proven.)
// ---------------------------------------------------------------------------
__global__ __launch_bounds__(128) void attn_kernel(
    const float* __restrict__ q, const float* __restrict__ k,
    const float* __restrict__ v, const float* __restrict__ mask,
    float* __restrict__ wa)
{
    extern __shared__ float sm[];
    float* Ksm = sm;
    float* Vsm = sm + 8192;
    float* msk = sm + 16384;
    int blk = blockIdx.x;
    int s = blk >> 2, h = blk & 3;
    size_t plane = (size_t)blk * PLANE;

    const float4* kp = (const float4*)(k + plane);
    const float4* vp = (const float4*)(v + plane);
    for (int i = threadIdx.x; i < PLANE/4; i += 128) {
        ((float4*)Ksm)[i] = kp[i];
        ((float4*)Vsm)[i] = vp[i];
    }
    for (int i = threadIdx.x; i < 256; i += 128) msk[i] = mask[i];
    __syncthreads();

    int q0 = threadIdx.x;
    u64 qa[16], qb[16];
    {
        const u64* p0 = (const u64*)(q + plane + (size_t)q0 * 32);
        const u64* p1 = (const u64*)(q + plane + (size_t)(q0 + 128) * 32);
        #pragma unroll
        for (int i = 0; i < 16; i++) { qa[i] = p0[i]; qb[i] = p1[i]; }
    }
    const float* b0 = g_biasT + (size_t)h * 65536 + q0;
    const float* b1 = b0 + 128;
    const float MASKVAL = -3.4028234663852886e34f;

    float ls0 = 0.f, ls1 = 0.f;
    u64 acc0[16], acc1[16];
    #pragma unroll
    for (int i = 0; i < 16; i++) { acc0[i] = 0ULL; acc1[i] = 0ULL; }

    #pragma unroll 2
    for (int kk = 0; kk < 256; kk++) {
        float bias0 = b0[kk*256];
        float bias1 = b1[kk*256];
        const ulonglong2* kr = (const ulonglong2*)(Ksm + kk*32);
        u64 d0a = 0ULL, d0b = 0ULL, d1a = 0ULL, d1b = 0ULL;
        #pragma unroll
        for (int j = 0; j < 8; j++) {
            ulonglong2 kq = kr[j];
            FMA2(d0a, qa[2*j],   kq.x, d0a);
            FMA2(d0b, qa[2*j+1], kq.y, d0b);
            FMA2(d1a, qb[2*j],   kq.x, d1a);
            FMA2(d1b, qb[2*j+1], kq.y, d1b);
        }
        float x0, x1, y0, y1;
        f2unpk(d0a, x0, x1); f2unpk(d0b, y0, y1);
        float dt0 = (x0 + x1) + (y0 + y1) + bias0;
        f2unpk(d1a, x0, x1); f2unpk(d1b, y0, y1);
        float dt1 = (x0 + x1) + (y0 + y1) + bias1;
        bool mk = (msk[kk] > 0.f);
        float e0 = __expf(mk ? dt0 : MASKVAL);
        float e1 = __expf(mk ? dt1 : MASKVAL);
        ls0 += e0; ls1 += e1;
        u64 e0p = f2pk(e0, e0);
        u64 e1p = f2pk(e1, e1);
        const ulonglong2* vr = (const ulonglong2*)(Vsm + kk*32);
        #pragma unroll
        for (int j = 0; j < 8; j++) {
            ulonglong2 vv = vr[j];
            FMA2(acc0[2*j],   e0p, vv.x, acc0[2*j]);
            FMA2(acc0[2*j+1], e0p, vv.y, acc0[2*j+1]);
            FMA2(acc1[2*j],   e1p, vv.x, acc1[2*j]);
            FMA2(acc1[2*j+1], e1p, vv.y, acc1[2*j+1]);
        }
    }

    float inv0 = 1.f / ls0, inv1 = 1.f / ls1;
    float* op0 = wa + ((size_t)(s*256 + q0)       * CC) + h * 32;
    float* op1 = wa + ((size_t)(s*256 + q0 + 128) * CC) + h * 32;
    #pragma unroll
    for (int j = 0; j < 8; j++) {
        float l0, h0, l1, h1;
        f2unpk(acc0[j*2],   l0, h0);
        f2unpk(acc0[j*2+1], l1, h1);
        *(float4*)(op0 + j*4) = make_float4(l0*inv0, h0*inv0, l1*inv0, h1*inv0);
        f2unpk(acc1[j*2],   l0, h0);
        f2unpk(acc1[j*2+1], l1, h1);
        *(float4*)(op1 + j*4) = make_float4(l0*inv1, h0*inv1, l1*inv1, h1*inv1);
    }
}

// ---------------------------------------------------------------------------
extern "C" void kernel_launch(void* const* d_in, const int* in_sizes, int n_in,
                              void* d_out, int out_size)
{
    const float* pair     = (const float*)d_in[0];
    const float* seq_mask = (const float*)d_in[1];
    const float* ln_g     = (const float*)d_in[2];
    const float* ln_b     = (const float*)d_in[3];
    const float* w_pair   = (const float*)d_in[4];
    const float* wq       = (const float*)d_in[5];
    const float* wk       = (const float*)d_in[6];
    const float* wv       = (const float*)d_in[7];
    const float* wg       = (const float*)d_in[8];
    const float* bg       = (const float*)d_in[9];
    const float* wo       = (const float*)d_in[10];
    const float* bo       = (const float*)d_in[11];
    const float* qw3 = (const float*)d_in[12]; const float* qb3 = (const float*)d_in[13];
    const float* qw5 = (const float*)d_in[14]; const float* qb5 = (const float*)d_in[15];
    const float* qw7 = (const float*)d_in[16]; const float* qb7 = (const float*)d_in[17];
    const float* kw3 = (const float*)d_in[18]; const float* kb3 = (const float*)d_in[19];
    const float* kw5 = (const float*)d_in[20]; const float* kb5 = (const float*)d_in[21];
    const float* kw7 = (const float*)d_in[22]; const float* kb7 = (const float*)d_in[23];
    const float* vw3 = (const float*)d_in[24]; const float* vb3 = (const float*)d_in[25];
    const float* vw5 = (const float*)d_in[26]; const float* vb5 = (const float*)d_in[27];
    const float* vw7 = (const float*)d_in[28]; const float* vb7 = (const float*)d_in[29];
    float* out = (float*)d_out;

    float *pqr, *pkr, *pvr, *pqc, *pkc, *pvc, *pgate, *pwa;
    cudaGetSymbolAddress((void**)&pqr,  g_qraw);
    cudaGetSymbolAddress((void**)&pkr,  g_kraw);
    cudaGetSymbolAddress((void**)&pvr,  g_vraw);
    cudaGetSymbolAddress((void**)&pqc,  g_qc);
    cudaGetSymbolAddress((void**)&pkc,  g_kc);
    cudaGetSymbolAddress((void**)&pvc,  g_vc);
    cudaGetSymbolAddress((void**)&pgate, g_gate);
    cudaGetSymbolAddress((void**)&pwa,  g_wa);

    const size_t asm_ = (size_t)(2*PLANE + 256) * sizeof(float);
    cudaFuncSetAttribute(mma_gemm_kernel, cudaFuncAttributeMaxDynamicSharedMemorySize, MMA_SMEM);
    cudaFuncSetAttribute(attn_kernel, cudaFuncAttributeMaxDynamicSharedMemorySize, (int)asm_);

    // 0. weight prep (5 CTAs, tiny)
    wprep_kernel<<<5, 256>>>(wq, wk, wv, wg, wo);

    // 1. LN + pair bias + pre-converted A tiles
    ln_bias_kernel<<<NROWS/8, 256>>>(pair, ln_g, ln_b, w_pair);

    // 2. projections (fast A path: pure copies)
    mma_gemm_kernel<<<NROWS/128, 256, MMA_SMEM>>>(1, nullptr, nullptr, 0, nullptr, pqr, 0);
    mma_gemm_kernel<<<NROWS/128, 256, MMA_SMEM>>>(1, nullptr, nullptr, 1, nullptr, pkr, 0);
    mma_gemm_kernel<<<NROWS/128, 256, MMA_SMEM>>>(1, nullptr, nullptr, 2, nullptr, pvr, 0);
    mma_gemm_kernel<<<NROWS/128, 256, MMA_SMEM>>>(1, nullptr, nullptr, 3, bg,      pgate, 1);

    // 3. fused q/k/v inception convs
    conv3_kernel<<<3*LL*HH, 256>>>(pqr, pkr, pvr, pqc, pkc, pvc,
                                   qw3, qb3, qw5, qb5, qw7, qb7,
                                   kw3, kb3, kw5, kb5, kw7, kb7,
                                   vw3, vb3, vw5, vb5, vw7, vb7);

    // 4. attention
    attn_kernel<<<LL*HH, 128, asm_>>>(pqc, pkc, pvc, seq_mask, pwa);

    // 5. (gate * wa) @ wo + bo  (slow A path with gate multiply, fast W)
    mma_gemm_kernel<<<NROWS/128, 256, MMA_SMEM>>>(0, pwa, pgate, 4, bo, out, 2);
}